// round 3
// baseline (speedup 1.0000x reference)
#include <cuda_runtime.h>
#include <cstdint>

// Problem constants (fixed by the dataset)
#define NN 100000
#define EE 1600000
#define SCAN_B 1024
#define MAX_BLOCKS 128   // ceil(NN/1024) = 98 <= 128

// Scratch (no cudaMalloc allowed)
__device__ int   g_deg[NN];
__device__ __align__(16) float g_dinv[NN];
__device__ int   g_start[NN + 1];
__device__ int   g_cursor[NN];
__device__ int   g_bsums[MAX_BLOCKS];
__device__ int   g_srcrow[EE];
__device__ __align__(16) float g_w[EE];
__device__ __align__(16) float g_bufA[(size_t)NN * 128];
__device__ __align__(16) float g_bufB[(size_t)NN * 128];

// ---------------- prologue: degree / dinv ----------------

__global__ void zero_deg_k(int* __restrict__ p, int n) {
    int i = blockIdx.x * blockDim.x + threadIdx.x;
    if (i < n) p[i] = 0;
}

__global__ void degree_k(const int* __restrict__ col, int* __restrict__ deg, int E) {
    int e = blockIdx.x * blockDim.x + threadIdx.x;
    if (e < E) atomicAdd(&deg[col[e]], 1);
}

__global__ void dinv_k(const int* __restrict__ deg, float* __restrict__ dinv, int n) {
    int i = blockIdx.x * blockDim.x + threadIdx.x;
    if (i < n) {
        int d = deg[i];
        dinv[i] = (d > 0) ? rsqrtf((float)d) : 0.0f;
    }
}

// ---------------- exclusive scan over degrees -> start offsets ----------------

__global__ void scan1_k(const int* __restrict__ deg, int* __restrict__ start,
                        int* __restrict__ bsums, int n) {
    __shared__ int s[SCAN_B];
    int i = blockIdx.x * SCAN_B + threadIdx.x;
    int v = (i < n) ? deg[i] : 0;
    s[threadIdx.x] = v;
    __syncthreads();
    for (int off = 1; off < SCAN_B; off <<= 1) {
        int t = (threadIdx.x >= off) ? s[threadIdx.x - off] : 0;
        __syncthreads();
        s[threadIdx.x] += t;
        __syncthreads();
    }
    if (i < n) start[i + 1] = s[threadIdx.x];   // inclusive, block-local
    if (threadIdx.x == SCAN_B - 1) bsums[blockIdx.x] = s[SCAN_B - 1];
}

__global__ void scan2_k(int* __restrict__ bsums, int nb) {
    __shared__ int s[MAX_BLOCKS];
    int v = (threadIdx.x < nb) ? bsums[threadIdx.x] : 0;
    s[threadIdx.x] = v;
    __syncthreads();
    for (int off = 1; off < MAX_BLOCKS; off <<= 1) {
        int t = (threadIdx.x >= off) ? s[threadIdx.x - off] : 0;
        __syncthreads();
        s[threadIdx.x] += t;
        __syncthreads();
    }
    if (threadIdx.x < nb) bsums[threadIdx.x] = s[threadIdx.x] - v;  // exclusive
}

__global__ void scan3_k(int* __restrict__ start, const int* __restrict__ bsums, int n) {
    int i = blockIdx.x * blockDim.x + threadIdx.x;
    if (i == 0) start[0] = 0;
    if (i < n) start[i + 1] += bsums[i >> 10];
}

__global__ void cursor_k(const int* __restrict__ start, int* __restrict__ cursor, int n) {
    int i = blockIdx.x * blockDim.x + threadIdx.x;
    if (i < n) cursor[i] = start[i];
}

// ---------------- CSC fill: per edge, place (row, norm) into col's bucket ----------------

__global__ void fill_k(const int* __restrict__ row, const int* __restrict__ col,
                       const float* __restrict__ dinv, int* __restrict__ cursor,
                       int* __restrict__ srcrow, float* __restrict__ w, int E) {
    int e = blockIdx.x * blockDim.x + threadIdx.x;
    if (e < E) {
        int r = row[e];
        int c = col[e];
        int pos = atomicAdd(&cursor[c], 1);
        srcrow[pos] = r;
        w[pos] = dinv[r] * dinv[c];
    }
}

// ---------------- dense GEMM: Y[n,FOUT] = X[n,128] @ W[128,FOUT] ----------------
// Block: 256 threads, tile = 64 rows x FOUT cols. W tile fully in SMEM.

template <int FOUT>
__global__ void gemm_k(const float* __restrict__ X, const float* __restrict__ W,
                       float* __restrict__ Y, int n) {
    extern __shared__ float sm[];
    float* Xs = sm;               // 64*128 floats
    float* Ws = sm + 64 * 128;    // 128*FOUT floats

    const int tid = threadIdx.x;
    const int row0 = blockIdx.x * 64;

    for (int i = tid * 4; i < 128 * FOUT; i += 256 * 4)
        *(float4*)(Ws + i) = *(const float4*)(W + i);

    for (int i = tid * 4; i < 64 * 128; i += 256 * 4) {
        int r = i >> 7;
        int c = i & 127;
        float4 v = make_float4(0.f, 0.f, 0.f, 0.f);
        if (row0 + r < n) v = *(const float4*)(X + (size_t)(row0 + r) * 128 + c);
        *(float4*)(Xs + i) = v;
    }
    __syncthreads();

    constexpr int CG = FOUT / 4;           // column groups of 4
    constexpr int TPR = 256 / CG;          // threads covering row dim
    constexpr int RPT = 64 / TPR;          // rows per thread
    const int cx = tid % CG;
    const int ry = tid / CG;

    float acc[RPT][4];
#pragma unroll
    for (int i = 0; i < RPT; i++)
        acc[i][0] = acc[i][1] = acc[i][2] = acc[i][3] = 0.f;

#pragma unroll 4
    for (int k = 0; k < 128; k++) {
        float4 w = *(float4*)(Ws + k * FOUT + cx * 4);
#pragma unroll
        for (int i = 0; i < RPT; i++) {
            float xv = Xs[(ry * RPT + i) * 128 + k];
            acc[i][0] += xv * w.x;
            acc[i][1] += xv * w.y;
            acc[i][2] += xv * w.z;
            acc[i][3] += xv * w.w;
        }
    }

#pragma unroll
    for (int i = 0; i < RPT; i++) {
        int r = row0 + ry * RPT + i;
        if (r < n)
            *(float4*)(Y + (size_t)r * FOUT + cx * 4) =
                make_float4(acc[i][0], acc[i][1], acc[i][2], acc[i][3]);
    }
}

// ---------------- aggregate: out[n] = sum_{e in CSC[n]} h[srcrow[e]] * w[e] + b, optional ReLU
// One warp per destination node; pure gather, no atomics.

template <int FOUT, bool RELU>
__global__ void agg_k(const float* __restrict__ h, const int* __restrict__ srcrow,
                      const float* __restrict__ w, const int* __restrict__ start,
                      const float* __restrict__ bias, float* __restrict__ out, int n) {
    int warp = (blockIdx.x * blockDim.x + threadIdx.x) >> 5;
    int lane = threadIdx.x & 31;
    if (warp >= n) return;

    int s = start[warp];
    int epos = start[warp + 1];

    if (FOUT == 128) {
        float4 a0 = make_float4(0.f, 0.f, 0.f, 0.f);
        float4 a1 = make_float4(0.f, 0.f, 0.f, 0.f);
        int k = s;
        for (; k + 2 <= epos; k += 2) {
            int   r0 = __ldg(srcrow + k),     r1 = __ldg(srcrow + k + 1);
            float w0 = __ldg(w + k),          w1 = __ldg(w + k + 1);
            float4 v0 = __ldg((const float4*)(h + (size_t)r0 * 128) + lane);
            float4 v1 = __ldg((const float4*)(h + (size_t)r1 * 128) + lane);
            a0.x += v0.x * w0; a0.y += v0.y * w0; a0.z += v0.z * w0; a0.w += v0.w * w0;
            a1.x += v1.x * w1; a1.y += v1.y * w1; a1.z += v1.z * w1; a1.w += v1.w * w1;
        }
        for (; k < epos; k++) {
            int r0 = __ldg(srcrow + k);
            float w0 = __ldg(w + k);
            float4 v0 = __ldg((const float4*)(h + (size_t)r0 * 128) + lane);
            a0.x += v0.x * w0; a0.y += v0.y * w0; a0.z += v0.z * w0; a0.w += v0.w * w0;
        }
        float4 bv = __ldg((const float4*)bias + lane);
        a0.x += a1.x + bv.x; a0.y += a1.y + bv.y;
        a0.z += a1.z + bv.z; a0.w += a1.w + bv.w;
        if (RELU) {
            a0.x = fmaxf(a0.x, 0.f); a0.y = fmaxf(a0.y, 0.f);
            a0.z = fmaxf(a0.z, 0.f); a0.w = fmaxf(a0.w, 0.f);
        }
        *((float4*)(out + (size_t)warp * 128) + lane) = a0;
    } else {  // FOUT == 64
        float2 a0 = make_float2(0.f, 0.f);
        float2 a1 = make_float2(0.f, 0.f);
        int k = s;
        for (; k + 2 <= epos; k += 2) {
            int   r0 = __ldg(srcrow + k),     r1 = __ldg(srcrow + k + 1);
            float w0 = __ldg(w + k),          w1 = __ldg(w + k + 1);
            float2 v0 = __ldg((const float2*)(h + (size_t)r0 * 64) + lane);
            float2 v1 = __ldg((const float2*)(h + (size_t)r1 * 64) + lane);
            a0.x += v0.x * w0; a0.y += v0.y * w0;
            a1.x += v1.x * w1; a1.y += v1.y * w1;
        }
        for (; k < epos; k++) {
            int r0 = __ldg(srcrow + k);
            float w0 = __ldg(w + k);
            float2 v0 = __ldg((const float2*)(h + (size_t)r0 * 64) + lane);
            a0.x += v0.x * w0; a0.y += v0.y * w0;
        }
        float2 bv = __ldg((const float2*)bias + lane);
        a0.x += a1.x + bv.x;
        a0.y += a1.y + bv.y;
        *((float2*)(out + (size_t)warp * 64) + lane) = a0;
    }
}

// ---------------- launch ----------------

extern "C" void kernel_launch(void* const* d_in, const int* in_sizes, int n_in,
                              void* d_out, int out_size) {
    const float* x  = (const float*)d_in[0];
    const int*   ei = (const int*)d_in[1];      // int32! (JAX x64 disabled)
    const float* W1 = (const float*)d_in[2];
    const float* b1 = (const float*)d_in[3];
    const float* W2 = (const float*)d_in[4];
    const float* b2 = (const float*)d_in[5];
    const float* W3 = (const float*)d_in[6];
    const float* b3 = (const float*)d_in[7];
    float* out = (float*)d_out;

    const int N = in_sizes[0] / 128;
    const int E = in_sizes[1] / 2;
    const int* row = ei;
    const int* col = ei + E;

    int *deg, *start, *cursor, *bsums, *srcrow;
    float *dinv, *w, *bufA, *bufB;
    cudaGetSymbolAddress((void**)&deg,    g_deg);
    cudaGetSymbolAddress((void**)&dinv,   g_dinv);
    cudaGetSymbolAddress((void**)&start,  g_start);
    cudaGetSymbolAddress((void**)&cursor, g_cursor);
    cudaGetSymbolAddress((void**)&bsums,  g_bsums);
    cudaGetSymbolAddress((void**)&srcrow, g_srcrow);
    cudaGetSymbolAddress((void**)&w,      g_w);
    cudaGetSymbolAddress((void**)&bufA,   g_bufA);
    cudaGetSymbolAddress((void**)&bufB,   g_bufB);

    const int SMEM128 = (64 * 128 + 128 * 128) * 4;  // 96 KB
    const int SMEM64  = (64 * 128 + 128 * 64) * 4;   // 64 KB
    cudaFuncSetAttribute(gemm_k<128>, cudaFuncAttributeMaxDynamicSharedMemorySize, SMEM128);
    cudaFuncSetAttribute(gemm_k<64>,  cudaFuncAttributeMaxDynamicSharedMemorySize, SMEM64);

    const int TB = 256;
    const int gN  = (N + TB - 1) / TB;
    const int gE  = (E + TB - 1) / TB;
    const int gW  = ((size_t)N * 32 + TB - 1) / TB;  // warp-per-node grid
    const int gG  = (N + 63) / 64;
    const int nb  = (N + SCAN_B - 1) / SCAN_B;       // 98

    // ---- CSC build ----
    zero_deg_k<<<gN, TB>>>(deg, N);
    degree_k<<<gE, TB>>>(col, deg, E);
    dinv_k<<<gN, TB>>>(deg, dinv, N);
    scan1_k<<<nb, SCAN_B>>>(deg, start, bsums, N);
    scan2_k<<<1, MAX_BLOCKS>>>(bsums, nb);
    scan3_k<<<gN, TB>>>(start, bsums, N);
    cursor_k<<<gN, TB>>>(start, cursor, N);
    fill_k<<<gE, TB>>>(row, col, dinv, cursor, srcrow, w, E);

    // ---- layer 1: relu(agg(x@W1) + b1) ----
    gemm_k<128><<<gG, TB, SMEM128>>>(x, W1, bufA, N);
    agg_k<128, true><<<gW, TB>>>(bufA, srcrow, w, start, b1, bufB, N);

    // ---- layer 2: relu(agg(h@W2) + b2) ----
    gemm_k<128><<<gG, TB, SMEM128>>>(bufB, W2, bufA, N);
    agg_k<128, true><<<gW, TB>>>(bufA, srcrow, w, start, b2, bufB, N);

    // ---- layer 3: agg(h@W3) + b3 -> d_out ----
    gemm_k<64><<<gG, TB, SMEM64>>>(bufB, W3, bufA, N);
    agg_k<64, false><<<gW, TB>>>(bufA, srcrow, w, start, b3, out, N);
}

// round 4
// speedup vs baseline: 1.1537x; 1.1537x over previous
#include <cuda_runtime.h>
#include <cuda_fp16.h>
#include <cstdint>

// Problem constants (fixed by the dataset)
#define NN 100000
#define EE 1600000
#define SCAN_B 1024
#define MAX_BLOCKS 128   // ceil(NN/1024) = 98 <= 128

// Scratch (no cudaMalloc allowed)
__device__ int   g_deg[NN];
__device__ __align__(16) float g_dinv[NN];
__device__ int   g_start[NN + 1];
__device__ int   g_cursor[NN];
__device__ int   g_bsums[MAX_BLOCKS];
__device__ int   g_srcrow[EE];
__device__ __align__(16) float  g_w[EE];
__device__ __align__(16) __half g_h[(size_t)NN * 128];     // GEMM output (fp16)
__device__ __align__(16) float  g_act[(size_t)NN * 128];   // inter-layer activations (fp32)

// ---------------- prologue: degree / dinv ----------------

__global__ void zero_deg_k(int* __restrict__ p, int n) {
    int i = blockIdx.x * blockDim.x + threadIdx.x;
    if (i < n) p[i] = 0;
}

__global__ void degree_k(const int* __restrict__ col, int* __restrict__ deg, int E) {
    int e = blockIdx.x * blockDim.x + threadIdx.x;
    if (e < E) atomicAdd(&deg[col[e]], 1);
}

__global__ void dinv_k(const int* __restrict__ deg, float* __restrict__ dinv, int n) {
    int i = blockIdx.x * blockDim.x + threadIdx.x;
    if (i < n) {
        int d = deg[i];
        dinv[i] = (d > 0) ? rsqrtf((float)d) : 0.0f;
    }
}

// ---------------- exclusive scan over degrees -> start offsets ----------------

__global__ void scan1_k(const int* __restrict__ deg, int* __restrict__ start,
                        int* __restrict__ bsums, int n) {
    __shared__ int s[SCAN_B];
    int i = blockIdx.x * SCAN_B + threadIdx.x;
    int v = (i < n) ? deg[i] : 0;
    s[threadIdx.x] = v;
    __syncthreads();
    for (int off = 1; off < SCAN_B; off <<= 1) {
        int t = (threadIdx.x >= off) ? s[threadIdx.x - off] : 0;
        __syncthreads();
        s[threadIdx.x] += t;
        __syncthreads();
    }
    if (i < n) start[i + 1] = s[threadIdx.x];   // inclusive, block-local
    if (threadIdx.x == SCAN_B - 1) bsums[blockIdx.x] = s[SCAN_B - 1];
}

__global__ void scan2_k(int* __restrict__ bsums, int nb) {
    __shared__ int s[MAX_BLOCKS];
    int v = (threadIdx.x < nb) ? bsums[threadIdx.x] : 0;
    s[threadIdx.x] = v;
    __syncthreads();
    for (int off = 1; off < MAX_BLOCKS; off <<= 1) {
        int t = (threadIdx.x >= off) ? s[threadIdx.x - off] : 0;
        __syncthreads();
        s[threadIdx.x] += t;
        __syncthreads();
    }
    if (threadIdx.x < nb) bsums[threadIdx.x] = s[threadIdx.x] - v;  // exclusive
}

__global__ void scan3_k(int* __restrict__ start, const int* __restrict__ bsums, int n) {
    int i = blockIdx.x * blockDim.x + threadIdx.x;
    if (i == 0) start[0] = 0;
    if (i < n) start[i + 1] += bsums[i >> 10];
}

__global__ void cursor_k(const int* __restrict__ start, int* __restrict__ cursor, int n) {
    int i = blockIdx.x * blockDim.x + threadIdx.x;
    if (i < n) cursor[i] = start[i];
}

// ---------------- CSC fill ----------------

__global__ void fill_k(const int* __restrict__ row, const int* __restrict__ col,
                       const float* __restrict__ dinv, int* __restrict__ cursor,
                       int* __restrict__ srcrow, float* __restrict__ w, int E) {
    int e = blockIdx.x * blockDim.x + threadIdx.x;
    if (e < E) {
        int r = row[e];
        int c = col[e];
        int pos = atomicAdd(&cursor[c], 1);
        srcrow[pos] = r;
        w[pos] = dinv[r] * dinv[c];
    }
}

// ---------------- dense GEMM: H[n,FOUT] = fp16( X[n,128] @ W[128,FOUT] ) --------
// 256 threads, tile = 64 rows x FOUT cols. Packed f32x2 FMA (FFMA2): the two
// 32-bit halves carry even-k / odd-k partial sums; horizontal add at the end.
// W stored transposed in smem with pitch 130 so k-pairs are contiguous LDS.64.

#define WPITCH 130

template <int FOUT>
__global__ void gemm_k(const float* __restrict__ X, const float* __restrict__ W,
                       __half* __restrict__ H, int n) {
    extern __shared__ float sm[];
    float* Xs = sm;                 // 64 x 128
    float* Wt = sm + 64 * 128;      // FOUT x WPITCH (transposed)

    const int tid = threadIdx.x;
    const int warp = tid >> 5;
    const int lane = tid & 31;
    const int row0 = blockIdx.x * 64;

    // Load W transposed: Wt[c][k] = W[k][c]
    for (int i = tid; i < 128 * FOUT; i += 256) {
        int k = i / FOUT, c = i % FOUT;
        Wt[c * WPITCH + k] = W[i];
    }
    // Load X tile (row-major, zero-fill OOB)
    for (int i = tid * 4; i < 64 * 128; i += 256 * 4) {
        int r = i >> 7, c = i & 127;
        float4 v = make_float4(0.f, 0.f, 0.f, 0.f);
        if (row0 + r < n) v = *(const float4*)(X + (size_t)(row0 + r) * 128 + c);
        *(float4*)(Xs + i) = v;
    }
    __syncthreads();

    constexpr int NJ = FOUT / 32;   // column groups: col = j*32 + lane
    unsigned long long acc[8][NJ];
#pragma unroll
    for (int i = 0; i < 8; i++)
#pragma unroll
        for (int j = 0; j < NJ; j++) acc[i][j] = 0ull;

    const float* xbase = Xs + warp * 8 * 128;

#pragma unroll 2
    for (int k2 = 0; k2 < 64; k2++) {
        unsigned long long xv[8];
#pragma unroll
        for (int i = 0; i < 8; i++)
            xv[i] = *(const unsigned long long*)(xbase + i * 128 + k2 * 2);
#pragma unroll
        for (int j = 0; j < NJ; j++) {
            unsigned long long wv =
                *(const unsigned long long*)(Wt + (j * 32 + lane) * WPITCH + k2 * 2);
#pragma unroll
            for (int i = 0; i < 8; i++)
                asm("fma.rn.f32x2 %0, %1, %2, %0;"
                    : "+l"(acc[i][j]) : "l"(xv[i]), "l"(wv));
        }
    }

#pragma unroll
    for (int i = 0; i < 8; i++) {
        int r = row0 + warp * 8 + i;
        if (r < n) {
#pragma unroll
            for (int j = 0; j < NJ; j++) {
                float lo, hi;
                asm("mov.b64 {%0, %1}, %2;" : "=f"(lo), "=f"(hi) : "l"(acc[i][j]));
                H[(size_t)r * FOUT + j * 32 + lane] = __float2half_rn(lo + hi);
            }
        }
    }
}

// ---------------- aggregate (fp16 gather, fp32 accumulate) ----------------
// One warp per destination node; pure gather, no atomics.

template <bool RELU>
__global__ void agg128_k(const __half* __restrict__ h, const int* __restrict__ srcrow,
                         const float* __restrict__ w, const int* __restrict__ start,
                         const float* __restrict__ bias, float* __restrict__ out, int n) {
    int node = (blockIdx.x * blockDim.x + threadIdx.x) >> 5;
    int lane = threadIdx.x & 31;
    if (node >= n) return;

    int s = start[node];
    int e = start[node + 1];
    const uint2* hb = (const uint2*)h;   // 8B = 4 halves per lane; row = 32 uint2

    float a0x = 0.f, a0y = 0.f, a0z = 0.f, a0w = 0.f;
    float a1x = 0.f, a1y = 0.f, a1z = 0.f, a1w = 0.f;

    int k = s;
    for (; k + 2 <= e; k += 2) {
        int   r0 = __ldg(srcrow + k),  r1 = __ldg(srcrow + k + 1);
        float w0 = __ldg(w + k),       w1 = __ldg(w + k + 1);
        uint2 v0 = __ldg(hb + (size_t)r0 * 32 + lane);
        uint2 v1 = __ldg(hb + (size_t)r1 * 32 + lane);
        float2 f00 = __half22float2(*(const half2*)&v0.x);
        float2 f01 = __half22float2(*(const half2*)&v0.y);
        float2 f10 = __half22float2(*(const half2*)&v1.x);
        float2 f11 = __half22float2(*(const half2*)&v1.y);
        a0x += f00.x * w0; a0y += f00.y * w0; a0z += f01.x * w0; a0w += f01.y * w0;
        a1x += f10.x * w1; a1y += f10.y * w1; a1z += f11.x * w1; a1w += f11.y * w1;
    }
    for (; k < e; k++) {
        int   r0 = __ldg(srcrow + k);
        float w0 = __ldg(w + k);
        uint2 v0 = __ldg(hb + (size_t)r0 * 32 + lane);
        float2 f00 = __half22float2(*(const half2*)&v0.x);
        float2 f01 = __half22float2(*(const half2*)&v0.y);
        a0x += f00.x * w0; a0y += f00.y * w0; a0z += f01.x * w0; a0w += f01.y * w0;
    }

    float4 bv = __ldg((const float4*)bias + lane);
    a0x += a1x + bv.x; a0y += a1y + bv.y;
    a0z += a1z + bv.z; a0w += a1w + bv.w;
    if (RELU) {
        a0x = fmaxf(a0x, 0.f); a0y = fmaxf(a0y, 0.f);
        a0z = fmaxf(a0z, 0.f); a0w = fmaxf(a0w, 0.f);
    }
    *((float4*)(out + (size_t)node * 128) + lane) = make_float4(a0x, a0y, a0z, a0w);
}

__global__ void agg64_k(const __half* __restrict__ h, const int* __restrict__ srcrow,
                        const float* __restrict__ w, const int* __restrict__ start,
                        const float* __restrict__ bias, float* __restrict__ out, int n) {
    int node = (blockIdx.x * blockDim.x + threadIdx.x) >> 5;
    int lane = threadIdx.x & 31;
    if (node >= n) return;

    int s = start[node];
    int e = start[node + 1];
    const half2* hb = (const half2*)h;   // row = 32 half2

    float a0x = 0.f, a0y = 0.f, a1x = 0.f, a1y = 0.f;

    int k = s;
    for (; k + 2 <= e; k += 2) {
        int   r0 = __ldg(srcrow + k),  r1 = __ldg(srcrow + k + 1);
        float w0 = __ldg(w + k),       w1 = __ldg(w + k + 1);
        float2 f0 = __half22float2(__ldg(hb + (size_t)r0 * 32 + lane));
        float2 f1 = __half22float2(__ldg(hb + (size_t)r1 * 32 + lane));
        a0x += f0.x * w0; a0y += f0.y * w0;
        a1x += f1.x * w1; a1y += f1.y * w1;
    }
    for (; k < e; k++) {
        int   r0 = __ldg(srcrow + k);
        float w0 = __ldg(w + k);
        float2 f0 = __half22float2(__ldg(hb + (size_t)r0 * 32 + lane));
        a0x += f0.x * w0; a0y += f0.y * w0;
    }

    float2 bv = __ldg((const float2*)bias + lane);
    a0x += a1x + bv.x;
    a0y += a1y + bv.y;
    *((float2*)(out + (size_t)node * 64) + lane) = make_float2(a0x, a0y);
}

// ---------------- launch ----------------

extern "C" void kernel_launch(void* const* d_in, const int* in_sizes, int n_in,
                              void* d_out, int out_size) {
    const float* x  = (const float*)d_in[0];
    const int*   ei = (const int*)d_in[1];      // int32 (JAX x64 disabled)
    const float* W1 = (const float*)d_in[2];
    const float* b1 = (const float*)d_in[3];
    const float* W2 = (const float*)d_in[4];
    const float* b2 = (const float*)d_in[5];
    const float* W3 = (const float*)d_in[6];
    const float* b3 = (const float*)d_in[7];
    float* out = (float*)d_out;

    const int N = in_sizes[0] / 128;
    const int E = in_sizes[1] / 2;
    const int* row = ei;
    const int* col = ei + E;

    int *deg, *start, *cursor, *bsums, *srcrow;
    float *dinv, *w, *act;
    __half* h;
    cudaGetSymbolAddress((void**)&deg,    g_deg);
    cudaGetSymbolAddress((void**)&dinv,   g_dinv);
    cudaGetSymbolAddress((void**)&start,  g_start);
    cudaGetSymbolAddress((void**)&cursor, g_cursor);
    cudaGetSymbolAddress((void**)&bsums,  g_bsums);
    cudaGetSymbolAddress((void**)&srcrow, g_srcrow);
    cudaGetSymbolAddress((void**)&w,      g_w);
    cudaGetSymbolAddress((void**)&h,      g_h);
    cudaGetSymbolAddress((void**)&act,    g_act);

    const int SMEM128 = (64 * 128 + 128 * WPITCH) * 4;  // ~97 KB
    const int SMEM64  = (64 * 128 + 64 * WPITCH) * 4;   // ~65 KB
    cudaFuncSetAttribute(gemm_k<128>, cudaFuncAttributeMaxDynamicSharedMemorySize, SMEM128);
    cudaFuncSetAttribute(gemm_k<64>,  cudaFuncAttributeMaxDynamicSharedMemorySize, SMEM64);

    const int TB = 256;
    const int gN  = (N + TB - 1) / TB;
    const int gE  = (E + TB - 1) / TB;
    const int gW  = ((size_t)N * 32 + TB - 1) / TB;  // warp-per-node grid
    const int gG  = (N + 63) / 64;
    const int nb  = (N + SCAN_B - 1) / SCAN_B;       // 98

    // ---- CSC build ----
    zero_deg_k<<<gN, TB>>>(deg, N);
    degree_k<<<gE, TB>>>(col, deg, E);
    dinv_k<<<gN, TB>>>(deg, dinv, N);
    scan1_k<<<nb, SCAN_B>>>(deg, start, bsums, N);
    scan2_k<<<1, MAX_BLOCKS>>>(bsums, nb);
    scan3_k<<<gN, TB>>>(start, bsums, N);
    cursor_k<<<gN, TB>>>(start, cursor, N);
    fill_k<<<gE, TB>>>(row, col, dinv, cursor, srcrow, w, E);

    // ---- layer 1: relu(agg(x@W1) + b1) ----
    gemm_k<128><<<gG, TB, SMEM128>>>(x, W1, h, N);
    agg128_k<true><<<gW, TB>>>(h, srcrow, w, start, b1, act, N);

    // ---- layer 2: relu(agg(h@W2) + b2) ----
    gemm_k<128><<<gG, TB, SMEM128>>>(act, W2, h, N);
    agg128_k<true><<<gW, TB>>>(h, srcrow, w, start, b2, act, N);

    // ---- layer 3: agg(h@W3) + b3 -> d_out ----
    gemm_k<64><<<gG, TB, SMEM64>>>(act, W3, h, N);
    agg64_k<<<gW, TB>>>(h, srcrow, w, start, b3, out, N);
}

// round 6
// speedup vs baseline: 1.2371x; 1.0723x over previous
#include <cuda_runtime.h>
#include <cuda_fp16.h>
#include <cstdint>

// Problem constants (fixed by the dataset)
#define NN 100000
#define EE 1600000
#define SCAN_B 1024
#define MAX_BLOCKS 128   // ceil(NN/1024) = 98 <= 128

// Scratch (no cudaMalloc allowed)
__device__ int   g_deg[NN];
__device__ __align__(16) float g_dinv[NN];
__device__ int   g_start[NN + 1];
__device__ int   g_cursor[NN];
__device__ int   g_bsums[MAX_BLOCKS];
__device__ int   g_srcrow[EE];
__device__ __align__(16) float  g_w[EE];
__device__ __align__(16) __half g_h[(size_t)NN * 128];     // GEMM output (fp16)
__device__ __align__(16) float  g_act[(size_t)NN * 128];   // inter-layer activations (fp32)

// ---------------- prologue ----------------

__global__ void zero_deg_k(int* __restrict__ p, int n) {
    int i = blockIdx.x * blockDim.x + threadIdx.x;
    if (i < n) p[i] = 0;
}

__global__ void degree_k(const int* __restrict__ col, int* __restrict__ deg, int E) {
    int e = blockIdx.x * blockDim.x + threadIdx.x;
    if (e < E) atomicAdd(&deg[col[e]], 1);
}

// scan over degrees (block-local inclusive) + dinv computation fused
__global__ void scan1_dinv_k(const int* __restrict__ deg, int* __restrict__ start,
                             int* __restrict__ bsums, float* __restrict__ dinv, int n) {
    __shared__ int s[SCAN_B];
    int i = blockIdx.x * SCAN_B + threadIdx.x;
    int v = (i < n) ? deg[i] : 0;
    if (i < n) dinv[i] = (v > 0) ? rsqrtf((float)v) : 0.0f;
    s[threadIdx.x] = v;
    __syncthreads();
    for (int off = 1; off < SCAN_B; off <<= 1) {
        int t = (threadIdx.x >= off) ? s[threadIdx.x - off] : 0;
        __syncthreads();
        s[threadIdx.x] += t;
        __syncthreads();
    }
    if (i < n) start[i + 1] = s[threadIdx.x];
    if (threadIdx.x == SCAN_B - 1) bsums[blockIdx.x] = s[SCAN_B - 1];
}

__global__ void scan2_k(int* __restrict__ bsums, int nb) {
    __shared__ int s[MAX_BLOCKS];
    int v = (threadIdx.x < nb) ? bsums[threadIdx.x] : 0;
    s[threadIdx.x] = v;
    __syncthreads();
    for (int off = 1; off < MAX_BLOCKS; off <<= 1) {
        int t = (threadIdx.x >= off) ? s[threadIdx.x - off] : 0;
        __syncthreads();
        s[threadIdx.x] += t;
        __syncthreads();
    }
    if (threadIdx.x < nb) bsums[threadIdx.x] = s[threadIdx.x] - v;  // exclusive
}

// apply block offsets + init cursor (fused)
__global__ void scan3_cursor_k(int* __restrict__ start, const int* __restrict__ bsums,
                               int* __restrict__ cursor, int n) {
    int i = blockIdx.x * blockDim.x + threadIdx.x;
    if (i < n) {
        int v = start[i + 1] + bsums[i >> 10];
        start[i + 1] = v;
        if (i + 1 < n) cursor[i + 1] = v;
        if (i == 0) { start[0] = 0; cursor[0] = 0; }
    }
}

__global__ void fill_k(const int* __restrict__ row, const int* __restrict__ col,
                       const float* __restrict__ dinv, int* __restrict__ cursor,
                       int* __restrict__ srcrow, float* __restrict__ w, int E) {
    int e = blockIdx.x * blockDim.x + threadIdx.x;
    if (e < E) {
        int r = row[e];
        int c = col[e];
        int pos = atomicAdd(&cursor[c], 1);
        srcrow[pos] = r;
        w[pos] = dinv[r] * dinv[c];
    }
}

// ---------------- dense GEMM: H[n,FOUT] = fp16( X[n,128] @ W[128,FOUT] ) --------
// 256 threads, tile = 64 rows x FOUT cols. Packed f32x2 FMA (FFMA2), even/odd-k
// partial sums. W transposed in smem, pitch 132 (16B-aligned rows, conflict-free
// LDS.128). Inner loop consumes 2 k-pairs (4 k) per iteration via float4 loads.

#define WPITCH 132

template <int FOUT>
__global__ void gemm_k(const float* __restrict__ X, const float* __restrict__ W,
                       __half* __restrict__ H, int n) {
    extern __shared__ float sm[];
    float* Xs = sm;                 // 64 x 128
    float* Wt = sm + 64 * 128;      // FOUT x WPITCH (transposed)

    const int tid = threadIdx.x;
    const int warp = tid >> 5;
    const int lane = tid & 31;
    const int row0 = blockIdx.x * 64;

    // Load W transposed: Wt[c][k] = W[k][c]
    for (int i = tid; i < 128 * FOUT; i += 256) {
        int k = i / FOUT, c = i % FOUT;
        Wt[c * WPITCH + k] = W[i];
    }
    // Load X tile (row-major, zero-fill OOB)
    for (int i = tid * 4; i < 64 * 128; i += 256 * 4) {
        int r = i >> 7, c = i & 127;
        float4 v = make_float4(0.f, 0.f, 0.f, 0.f);
        if (row0 + r < n) v = *(const float4*)(X + (size_t)(row0 + r) * 128 + c);
        *(float4*)(Xs + i) = v;
    }
    __syncthreads();

    constexpr int NJ = FOUT / 32;   // column groups: col = j*32 + lane
    unsigned long long acc[8][NJ];
#pragma unroll
    for (int i = 0; i < 8; i++)
#pragma unroll
        for (int j = 0; j < NJ; j++) acc[i][j] = 0ull;

    const float* xbase = Xs + warp * 8 * 128;

#pragma unroll 2
    for (int k4 = 0; k4 < 32; k4++) {      // 4 k values per iteration
        // X: two packed k-pairs per row (16B broadcast loads)
        unsigned long long xa[8], xb[8];
#pragma unroll
        for (int i = 0; i < 8; i++) {
            float4 xv = *(const float4*)(xbase + i * 128 + k4 * 4);
            xa[i] = *(const unsigned long long*)&xv.x;
            xb[i] = *(const unsigned long long*)&xv.z;
        }
#pragma unroll
        for (int j = 0; j < NJ; j++) {
            float4 wv = *(const float4*)(Wt + (j * 32 + lane) * WPITCH + k4 * 4);
            unsigned long long wa = *(const unsigned long long*)&wv.x;
            unsigned long long wb = *(const unsigned long long*)&wv.z;
#pragma unroll
            for (int i = 0; i < 8; i++) {
                asm("fma.rn.f32x2 %0, %1, %2, %0;"
                    : "+l"(acc[i][j]) : "l"(xa[i]), "l"(wa));
                asm("fma.rn.f32x2 %0, %1, %2, %0;"
                    : "+l"(acc[i][j]) : "l"(xb[i]), "l"(wb));
            }
        }
    }

#pragma unroll
    for (int i = 0; i < 8; i++) {
        int r = row0 + warp * 8 + i;
        if (r < n) {
#pragma unroll
            for (int j = 0; j < NJ; j++) {
                float lo, hi;
                asm("mov.b64 {%0, %1}, %2;" : "=f"(lo), "=f"(hi) : "l"(acc[i][j]));
                H[(size_t)r * FOUT + j * 32 + lane] = __float2half_rn(lo + hi);
            }
        }
    }
}

// ---------------- aggregate (fp16 gather, fp32 accumulate, MLP=4) ----------------

template <bool RELU>
__global__ void agg128_k(const __half* __restrict__ h, const int* __restrict__ srcrow,
                         const float* __restrict__ w, const int* __restrict__ start,
                         const float* __restrict__ bias, float* __restrict__ out, int n) {
    int node = (blockIdx.x * blockDim.x + threadIdx.x) >> 5;
    int lane = threadIdx.x & 31;
    if (node >= n) return;

    int s = start[node];
    int e = start[node + 1];
    const uint2* hb = (const uint2*)h;   // 8B = 4 halves per lane; row = 32 uint2

    float a0x = 0.f, a0y = 0.f, a0z = 0.f, a0w = 0.f;
    float a1x = 0.f, a1y = 0.f, a1z = 0.f, a1w = 0.f;

    int k = s;
    for (; k + 4 <= e; k += 4) {
        int   r0 = __ldg(srcrow + k),     r1 = __ldg(srcrow + k + 1);
        int   r2 = __ldg(srcrow + k + 2), r3 = __ldg(srcrow + k + 3);
        float w0 = __ldg(w + k),          w1 = __ldg(w + k + 1);
        float w2 = __ldg(w + k + 2),      w3 = __ldg(w + k + 3);
        uint2 v0 = __ldg(hb + (size_t)r0 * 32 + lane);
        uint2 v1 = __ldg(hb + (size_t)r1 * 32 + lane);
        uint2 v2 = __ldg(hb + (size_t)r2 * 32 + lane);
        uint2 v3 = __ldg(hb + (size_t)r3 * 32 + lane);
        float2 f;
        f = __half22float2(*(const half2*)&v0.x); a0x += f.x * w0; a0y += f.y * w0;
        f = __half22float2(*(const half2*)&v0.y); a0z += f.x * w0; a0w += f.y * w0;
        f = __half22float2(*(const half2*)&v1.x); a1x += f.x * w1; a1y += f.y * w1;
        f = __half22float2(*(const half2*)&v1.y); a1z += f.x * w1; a1w += f.y * w1;
        f = __half22float2(*(const half2*)&v2.x); a0x += f.x * w2; a0y += f.y * w2;
        f = __half22float2(*(const half2*)&v2.y); a0z += f.x * w2; a0w += f.y * w2;
        f = __half22float2(*(const half2*)&v3.x); a1x += f.x * w3; a1y += f.y * w3;
        f = __half22float2(*(const half2*)&v3.y); a1z += f.x * w3; a1w += f.y * w3;
    }
    for (; k < e; k++) {
        int   r0 = __ldg(srcrow + k);
        float w0 = __ldg(w + k);
        uint2 v0 = __ldg(hb + (size_t)r0 * 32 + lane);
        float2 f;
        f = __half22float2(*(const half2*)&v0.x); a0x += f.x * w0; a0y += f.y * w0;
        f = __half22float2(*(const half2*)&v0.y); a0z += f.x * w0; a0w += f.y * w0;
    }

    float4 bv = __ldg((const float4*)bias + lane);
    a0x += a1x + bv.x; a0y += a1y + bv.y;
    a0z += a1z + bv.z; a0w += a1w + bv.w;
    if (RELU) {
        a0x = fmaxf(a0x, 0.f); a0y = fmaxf(a0y, 0.f);
        a0z = fmaxf(a0z, 0.f); a0w = fmaxf(a0w, 0.f);
    }
    *((float4*)(out + (size_t)node * 128) + lane) = make_float4(a0x, a0y, a0z, a0w);
}

__global__ void agg64_k(const __half* __restrict__ h, const int* __restrict__ srcrow,
                        const float* __restrict__ w, const int* __restrict__ start,
                        const float* __restrict__ bias, float* __restrict__ out, int n) {
    int node = (blockIdx.x * blockDim.x + threadIdx.x) >> 5;
    int lane = threadIdx.x & 31;
    if (node >= n) return;

    int s = start[node];
    int e = start[node + 1];
    const half2* hb = (const half2*)h;   // row = 32 half2

    float a0x = 0.f, a0y = 0.f, a1x = 0.f, a1y = 0.f;

    int k = s;
    for (; k + 4 <= e; k += 4) {
        int   r0 = __ldg(srcrow + k),     r1 = __ldg(srcrow + k + 1);
        int   r2 = __ldg(srcrow + k + 2), r3 = __ldg(srcrow + k + 3);
        float w0 = __ldg(w + k),          w1 = __ldg(w + k + 1);
        float w2 = __ldg(w + k + 2),      w3 = __ldg(w + k + 3);
        float2 f0 = __half22float2(__ldg(hb + (size_t)r0 * 32 + lane));
        float2 f1 = __half22float2(__ldg(hb + (size_t)r1 * 32 + lane));
        float2 f2 = __half22float2(__ldg(hb + (size_t)r2 * 32 + lane));
        float2 f3 = __half22float2(__ldg(hb + (size_t)r3 * 32 + lane));
        a0x += f0.x * w0; a0y += f0.y * w0;
        a1x += f1.x * w1; a1y += f1.y * w1;
        a0x += f2.x * w2; a0y += f2.y * w2;
        a1x += f3.x * w3; a1y += f3.y * w3;
    }
    for (; k < e; k++) {
        int   r0 = __ldg(srcrow + k);
        float w0 = __ldg(w + k);
        float2 f0 = __half22float2(__ldg(hb + (size_t)r0 * 32 + lane));
        a0x += f0.x * w0; a0y += f0.y * w0;
    }

    float2 bv = __ldg((const float2*)bias + lane);
    a0x += a1x + bv.x;
    a0y += a1y + bv.y;
    *((float2*)(out + (size_t)node * 64) + lane) = make_float2(a0x, a0y);
}

// ---------------- launch ----------------

extern "C" void kernel_launch(void* const* d_in, const int* in_sizes, int n_in,
                              void* d_out, int out_size) {
    const float* x  = (const float*)d_in[0];
    const int*   ei = (const int*)d_in[1];      // int32 (JAX x64 disabled)
    const float* W1 = (const float*)d_in[2];
    const float* b1 = (const float*)d_in[3];
    const float* W2 = (const float*)d_in[4];
    const float* b2 = (const float*)d_in[5];
    const float* W3 = (const float*)d_in[6];
    const float* b3 = (const float*)d_in[7];
    float* out = (float*)d_out;

    const int N = in_sizes[0] / 128;
    const int E = in_sizes[1] / 2;
    const int* row = ei;
    const int* col = ei + E;

    int *deg, *start, *cursor, *bsums, *srcrow;
    float *dinv, *w, *act;
    __half* h;
    cudaGetSymbolAddress((void**)&deg,    g_deg);
    cudaGetSymbolAddress((void**)&dinv,   g_dinv);
    cudaGetSymbolAddress((void**)&start,  g_start);
    cudaGetSymbolAddress((void**)&cursor, g_cursor);
    cudaGetSymbolAddress((void**)&bsums,  g_bsums);
    cudaGetSymbolAddress((void**)&srcrow, g_srcrow);
    cudaGetSymbolAddress((void**)&w,      g_w);
    cudaGetSymbolAddress((void**)&h,      g_h);
    cudaGetSymbolAddress((void**)&act,    g_act);

    const int SMEM128 = (64 * 128 + 128 * WPITCH) * 4;
    const int SMEM64  = (64 * 128 + 64 * WPITCH) * 4;
    cudaFuncSetAttribute(gemm_k<128>, cudaFuncAttributeMaxDynamicSharedMemorySize, SMEM128);
    cudaFuncSetAttribute(gemm_k<64>,  cudaFuncAttributeMaxDynamicSharedMemorySize, SMEM64);

    const int TB = 256;
    const int gN  = (N + TB - 1) / TB;
    const int gE  = (E + TB - 1) / TB;
    const int gW  = ((size_t)N * 32 + TB - 1) / TB;  // warp-per-node grid
    const int gG  = (N + 63) / 64;
    const int nb  = (N + SCAN_B - 1) / SCAN_B;       // 98

    // Launch order arranged so ncu (-s 5 -c 1) captures gemm_k<128> (index 5).
    zero_deg_k<<<gN, TB>>>(deg, N);                               // 0
    degree_k<<<gE, TB>>>(col, deg, E);                            // 1
    scan1_dinv_k<<<nb, SCAN_B>>>(deg, start, bsums, dinv, N);     // 2
    scan2_k<<<1, MAX_BLOCKS>>>(bsums, nb);                        // 3
    scan3_cursor_k<<<gN, TB>>>(start, bsums, cursor, N);          // 4
    gemm_k<128><<<gG, TB, SMEM128>>>(x, W1, h, N);                // 5  <- profiled
    fill_k<<<gE, TB>>>(row, col, dinv, cursor, srcrow, w, E);     // 6

    // ---- layer 1 ----
    agg128_k<true><<<gW, TB>>>(h, srcrow, w, start, b1, act, N);  // 7
    // ---- layer 2 ----
    gemm_k<128><<<gG, TB, SMEM128>>>(act, W2, h, N);              // 8
    agg128_k<true><<<gW, TB>>>(h, srcrow, w, start, b2, act, N);  // 9
    // ---- layer 3 ----
    gemm_k<64><<<gG, TB, SMEM64>>>(act, W3, h, N);                // 10
    agg64_k<<<gW, TB>>>(h, srcrow, w, start, b3, out, N);         // 11
}

// round 7
// speedup vs baseline: 1.8350x; 1.4833x over previous
#include <cuda_runtime.h>
#include <cuda_fp16.h>
#include <cstdint>

// Problem constants (fixed by the dataset)
#define NN 100000
#define EE 1600000
#define SCAN_B 1024
#define MAX_BLOCKS 128   // ceil(NN/1024) = 98 <= 128

// Scratch (no cudaMalloc allowed)
__device__ int   g_deg[NN];
__device__ __align__(16) float g_dinv[NN];
__device__ int   g_start[NN + 1];
__device__ int   g_cursor[NN];
__device__ int   g_bsums[MAX_BLOCKS];
__device__ int   g_srcrow[EE];
__device__ __align__(16) float  g_w[EE];
__device__ __align__(16) __half g_h[(size_t)NN * 128];     // GEMM output (fp16)
__device__ __align__(16) float  g_act[(size_t)NN * 128];   // inter-layer activations (fp32)

// ---------------- prologue ----------------

__global__ void zero_deg_k(int* __restrict__ p, int n) {
    int i = blockIdx.x * blockDim.x + threadIdx.x;
    if (i < n) p[i] = 0;
}

__global__ void degree_k(const int* __restrict__ col, int* __restrict__ deg, int E) {
    int e = blockIdx.x * blockDim.x + threadIdx.x;
    if (e < E) atomicAdd(&deg[col[e]], 1);
}

__global__ void scan1_dinv_k(const int* __restrict__ deg, int* __restrict__ start,
                             int* __restrict__ bsums, float* __restrict__ dinv, int n) {
    __shared__ int s[SCAN_B];
    int i = blockIdx.x * SCAN_B + threadIdx.x;
    int v = (i < n) ? deg[i] : 0;
    if (i < n) dinv[i] = (v > 0) ? rsqrtf((float)v) : 0.0f;
    s[threadIdx.x] = v;
    __syncthreads();
    for (int off = 1; off < SCAN_B; off <<= 1) {
        int t = (threadIdx.x >= off) ? s[threadIdx.x - off] : 0;
        __syncthreads();
        s[threadIdx.x] += t;
        __syncthreads();
    }
    if (i < n) start[i + 1] = s[threadIdx.x];
    if (threadIdx.x == SCAN_B - 1) bsums[blockIdx.x] = s[SCAN_B - 1];
}

__global__ void scan2_k(int* __restrict__ bsums, int nb) {
    __shared__ int s[MAX_BLOCKS];
    int v = (threadIdx.x < nb) ? bsums[threadIdx.x] : 0;
    s[threadIdx.x] = v;
    __syncthreads();
    for (int off = 1; off < MAX_BLOCKS; off <<= 1) {
        int t = (threadIdx.x >= off) ? s[threadIdx.x - off] : 0;
        __syncthreads();
        s[threadIdx.x] += t;
        __syncthreads();
    }
    if (threadIdx.x < nb) bsums[threadIdx.x] = s[threadIdx.x] - v;  // exclusive
}

__global__ void scan3_cursor_k(int* __restrict__ start, const int* __restrict__ bsums,
                               int* __restrict__ cursor, int n) {
    int i = blockIdx.x * blockDim.x + threadIdx.x;
    if (i < n) {
        int v = start[i + 1] + bsums[i >> 10];
        start[i + 1] = v;
        if (i + 1 < n) cursor[i + 1] = v;
        if (i == 0) { start[0] = 0; cursor[0] = 0; }
    }
}

__global__ void fill_k(const int* __restrict__ row, const int* __restrict__ col,
                       const float* __restrict__ dinv, int* __restrict__ cursor,
                       int* __restrict__ srcrow, float* __restrict__ w, int E) {
    int e = blockIdx.x * blockDim.x + threadIdx.x;
    if (e < E) {
        int r = row[e];
        int c = col[e];
        int pos = atomicAdd(&cursor[c], 1);
        srcrow[pos] = r;
        w[pos] = dinv[r] * dinv[c];
    }
}

// ---------------- tensor-core GEMM: H[n,FOUT] = fp16( X[n,128] @ W[128,FOUT] ) ----
// mma.sync m16n8k16 fp16 inputs, fp32 accumulate.
// 256 threads. FOUT=128: block tile 64x128 (warps 4x2). FOUT=64: 128x64 (warps 8x1).
// Xh/Wt in smem as fp16 with pitch 136 halves: fragment loads map to banks 4g+t,
// fully conflict-free.

__device__ __forceinline__ void mma16816(float* c,
    uint32_t a0, uint32_t a1, uint32_t a2, uint32_t a3,
    uint32_t b0, uint32_t b1) {
    asm volatile(
        "mma.sync.aligned.m16n8k16.row.col.f32.f16.f16.f32 "
        "{%0,%1,%2,%3}, {%4,%5,%6,%7}, {%8,%9}, {%0,%1,%2,%3};"
        : "+f"(c[0]), "+f"(c[1]), "+f"(c[2]), "+f"(c[3])
        : "r"(a0), "r"(a1), "r"(a2), "r"(a3), "r"(b0), "r"(b1));
}

template <int FOUT>
__global__ void gemm_k(const float* __restrict__ X, const float* __restrict__ W,
                       __half* __restrict__ H, int n) {
    constexpr int TM = (FOUT == 128) ? 64 : 128;  // rows per block
    constexpr int WN = FOUT / 64;                 // warps along N
    constexpr int XP = 136, WP = 136;             // smem pitches (halves)

    extern __shared__ __half smh[];
    __half* Xh = smh;              // TM x XP
    __half* Wt = smh + TM * XP;    // FOUT x WP  (transposed: Wt[c][k] = W[k][c])

    const int tid  = threadIdx.x;
    const int warp = tid >> 5;
    const int lane = tid & 31;
    const int g = lane >> 2;       // 0..7
    const int t = lane & 3;        // 0..3
    const int row0 = blockIdx.x * TM;

    // W -> Wt fp16 (coalesced global reads)
    for (int i = tid; i < 128 * FOUT; i += 256) {
        int k = i / FOUT, c = i % FOUT;
        Wt[c * WP + k] = __float2half_rn(W[i]);
    }
    // X -> Xh fp16 (8 cols per unit, float4 reads)
    for (int u = tid; u < TM * 16; u += 256) {
        int r = u >> 4, c8 = (u & 15) << 3;
        half2 h0, h1, h2, h3;
        if (row0 + r < n) {
            float4 f0 = *(const float4*)(X + (size_t)(row0 + r) * 128 + c8);
            float4 f1 = *(const float4*)(X + (size_t)(row0 + r) * 128 + c8 + 4);
            h0 = __floats2half2_rn(f0.x, f0.y);
            h1 = __floats2half2_rn(f0.z, f0.w);
            h2 = __floats2half2_rn(f1.x, f1.y);
            h3 = __floats2half2_rn(f1.z, f1.w);
        } else {
            h0 = h1 = h2 = h3 = __floats2half2_rn(0.f, 0.f);
        }
        half2* dst = (half2*)(Xh + r * XP + c8);
        dst[0] = h0; dst[1] = h1; dst[2] = h2; dst[3] = h3;
    }
    __syncthreads();

    const int wm = (warp / WN) * 16;   // warp row base within tile
    const int n0 = (warp % WN) * 64;   // warp col base

    float acc[8][4];
#pragma unroll
    for (int j = 0; j < 8; j++) {
        acc[j][0] = acc[j][1] = acc[j][2] = acc[j][3] = 0.f;
    }

#pragma unroll
    for (int ks = 0; ks < 8; ks++) {
        const int k0 = ks * 16;
        uint32_t a0 = *(const uint32_t*)(Xh + (wm + g)     * XP + k0 + 2 * t);
        uint32_t a1 = *(const uint32_t*)(Xh + (wm + g + 8) * XP + k0 + 2 * t);
        uint32_t a2 = *(const uint32_t*)(Xh + (wm + g)     * XP + k0 + 2 * t + 8);
        uint32_t a3 = *(const uint32_t*)(Xh + (wm + g + 8) * XP + k0 + 2 * t + 8);
#pragma unroll
        for (int j = 0; j < 8; j++) {
            const __half* wb = Wt + (n0 + j * 8 + g) * WP + k0 + 2 * t;
            uint32_t b0 = *(const uint32_t*)wb;
            uint32_t b1 = *(const uint32_t*)(wb + 8);
            mma16816(acc[j], a0, a1, a2, a3, b0, b1);
        }
    }

    // epilogue: c0,c1 -> (row wm+g, col n0+8j+2t); c2,c3 -> row +8
    const int r0i = row0 + wm + g;
#pragma unroll
    for (int j = 0; j < 8; j++) {
        int cidx = n0 + j * 8 + 2 * t;
        if (r0i < n)
            *(half2*)(H + (size_t)r0i * FOUT + cidx) =
                __floats2half2_rn(acc[j][0], acc[j][1]);
        if (r0i + 8 < n)
            *(half2*)(H + (size_t)(r0i + 8) * FOUT + cidx) =
                __floats2half2_rn(acc[j][2], acc[j][3]);
    }
}

// ---------------- aggregate (fp16 gather, fp32 accumulate, MLP=4) ----------------

template <bool RELU>
__global__ void agg128_k(const __half* __restrict__ h, const int* __restrict__ srcrow,
                         const float* __restrict__ w, const int* __restrict__ start,
                         const float* __restrict__ bias, float* __restrict__ out, int n) {
    int node = (blockIdx.x * blockDim.x + threadIdx.x) >> 5;
    int lane = threadIdx.x & 31;
    if (node >= n) return;

    int s = start[node];
    int e = start[node + 1];
    const uint2* hb = (const uint2*)h;   // 8B = 4 halves per lane; row = 32 uint2

    float a0x = 0.f, a0y = 0.f, a0z = 0.f, a0w = 0.f;
    float a1x = 0.f, a1y = 0.f, a1z = 0.f, a1w = 0.f;

    int k = s;
    for (; k + 4 <= e; k += 4) {
        int   r0 = __ldg(srcrow + k),     r1 = __ldg(srcrow + k + 1);
        int   r2 = __ldg(srcrow + k + 2), r3 = __ldg(srcrow + k + 3);
        float w0 = __ldg(w + k),          w1 = __ldg(w + k + 1);
        float w2 = __ldg(w + k + 2),      w3 = __ldg(w + k + 3);
        uint2 v0 = __ldg(hb + (size_t)r0 * 32 + lane);
        uint2 v1 = __ldg(hb + (size_t)r1 * 32 + lane);
        uint2 v2 = __ldg(hb + (size_t)r2 * 32 + lane);
        uint2 v3 = __ldg(hb + (size_t)r3 * 32 + lane);
        float2 f;
        f = __half22float2(*(const half2*)&v0.x); a0x += f.x * w0; a0y += f.y * w0;
        f = __half22float2(*(const half2*)&v0.y); a0z += f.x * w0; a0w += f.y * w0;
        f = __half22float2(*(const half2*)&v1.x); a1x += f.x * w1; a1y += f.y * w1;
        f = __half22float2(*(const half2*)&v1.y); a1z += f.x * w1; a1w += f.y * w1;
        f = __half22float2(*(const half2*)&v2.x); a0x += f.x * w2; a0y += f.y * w2;
        f = __half22float2(*(const half2*)&v2.y); a0z += f.x * w2; a0w += f.y * w2;
        f = __half22float2(*(const half2*)&v3.x); a1x += f.x * w3; a1y += f.y * w3;
        f = __half22float2(*(const half2*)&v3.y); a1z += f.x * w3; a1w += f.y * w3;
    }
    for (; k < e; k++) {
        int   r0 = __ldg(srcrow + k);
        float w0 = __ldg(w + k);
        uint2 v0 = __ldg(hb + (size_t)r0 * 32 + lane);
        float2 f;
        f = __half22float2(*(const half2*)&v0.x); a0x += f.x * w0; a0y += f.y * w0;
        f = __half22float2(*(const half2*)&v0.y); a0z += f.x * w0; a0w += f.y * w0;
    }

    float4 bv = __ldg((const float4*)bias + lane);
    a0x += a1x + bv.x; a0y += a1y + bv.y;
    a0z += a1z + bv.z; a0w += a1w + bv.w;
    if (RELU) {
        a0x = fmaxf(a0x, 0.f); a0y = fmaxf(a0y, 0.f);
        a0z = fmaxf(a0z, 0.f); a0w = fmaxf(a0w, 0.f);
    }
    *((float4*)(out + (size_t)node * 128) + lane) = make_float4(a0x, a0y, a0z, a0w);
}

__global__ void agg64_k(const __half* __restrict__ h, const int* __restrict__ srcrow,
                        const float* __restrict__ w, const int* __restrict__ start,
                        const float* __restrict__ bias, float* __restrict__ out, int n) {
    int node = (blockIdx.x * blockDim.x + threadIdx.x) >> 5;
    int lane = threadIdx.x & 31;
    if (node >= n) return;

    int s = start[node];
    int e = start[node + 1];
    const half2* hb = (const half2*)h;   // row = 32 half2

    float a0x = 0.f, a0y = 0.f, a1x = 0.f, a1y = 0.f;

    int k = s;
    for (; k + 4 <= e; k += 4) {
        int   r0 = __ldg(srcrow + k),     r1 = __ldg(srcrow + k + 1);
        int   r2 = __ldg(srcrow + k + 2), r3 = __ldg(srcrow + k + 3);
        float w0 = __ldg(w + k),          w1 = __ldg(w + k + 1);
        float w2 = __ldg(w + k + 2),      w3 = __ldg(w + k + 3);
        float2 f0 = __half22float2(__ldg(hb + (size_t)r0 * 32 + lane));
        float2 f1 = __half22float2(__ldg(hb + (size_t)r1 * 32 + lane));
        float2 f2 = __half22float2(__ldg(hb + (size_t)r2 * 32 + lane));
        float2 f3 = __half22float2(__ldg(hb + (size_t)r3 * 32 + lane));
        a0x += f0.x * w0; a0y += f0.y * w0;
        a1x += f1.x * w1; a1y += f1.y * w1;
        a0x += f2.x * w2; a0y += f2.y * w2;
        a1x += f3.x * w3; a1y += f3.y * w3;
    }
    for (; k < e; k++) {
        int   r0 = __ldg(srcrow + k);
        float w0 = __ldg(w + k);
        float2 f0 = __half22float2(__ldg(hb + (size_t)r0 * 32 + lane));
        a0x += f0.x * w0; a0y += f0.y * w0;
    }

    float2 bv = __ldg((const float2*)bias + lane);
    a0x += a1x + bv.x;
    a0y += a1y + bv.y;
    *((float2*)(out + (size_t)node * 64) + lane) = make_float2(a0x, a0y);
}

// ---------------- launch ----------------

extern "C" void kernel_launch(void* const* d_in, const int* in_sizes, int n_in,
                              void* d_out, int out_size) {
    const float* x  = (const float*)d_in[0];
    const int*   ei = (const int*)d_in[1];      // int32 (JAX x64 disabled)
    const float* W1 = (const float*)d_in[2];
    const float* b1 = (const float*)d_in[3];
    const float* W2 = (const float*)d_in[4];
    const float* b2 = (const float*)d_in[5];
    const float* W3 = (const float*)d_in[6];
    const float* b3 = (const float*)d_in[7];
    float* out = (float*)d_out;

    const int N = in_sizes[0] / 128;
    const int E = in_sizes[1] / 2;
    const int* row = ei;
    const int* col = ei + E;

    int *deg, *start, *cursor, *bsums, *srcrow;
    float *dinv, *w, *act;
    __half* h;
    cudaGetSymbolAddress((void**)&deg,    g_deg);
    cudaGetSymbolAddress((void**)&dinv,   g_dinv);
    cudaGetSymbolAddress((void**)&start,  g_start);
    cudaGetSymbolAddress((void**)&cursor, g_cursor);
    cudaGetSymbolAddress((void**)&bsums,  g_bsums);
    cudaGetSymbolAddress((void**)&srcrow, g_srcrow);
    cudaGetSymbolAddress((void**)&w,      g_w);
    cudaGetSymbolAddress((void**)&h,      g_h);
    cudaGetSymbolAddress((void**)&act,    g_act);

    // smem: (TM + FOUT) * 136 halves = 192*136*2 bytes for both configs
    const int SMEMG = 192 * 136 * 2;   // 52224 B
    cudaFuncSetAttribute(gemm_k<128>, cudaFuncAttributeMaxDynamicSharedMemorySize, SMEMG);
    cudaFuncSetAttribute(gemm_k<64>,  cudaFuncAttributeMaxDynamicSharedMemorySize, SMEMG);

    const int TB = 256;
    const int gN   = (N + TB - 1) / TB;
    const int gE   = (E + TB - 1) / TB;
    const int gW   = ((size_t)N * 32 + TB - 1) / TB;  // warp-per-node grid
    const int gG128 = (N + 63) / 64;
    const int gG64  = (N + 127) / 128;
    const int nb   = (N + SCAN_B - 1) / SCAN_B;       // 98

    // ---- CSC build ----
    zero_deg_k<<<gN, TB>>>(deg, N);
    degree_k<<<gE, TB>>>(col, deg, E);
    scan1_dinv_k<<<nb, SCAN_B>>>(deg, start, bsums, dinv, N);
    scan2_k<<<1, MAX_BLOCKS>>>(bsums, nb);
    scan3_cursor_k<<<gN, TB>>>(start, bsums, cursor, N);
    gemm_k<128><<<gG128, TB, SMEMG>>>(x, W1, h, N);   // independent of CSC; early
    fill_k<<<gE, TB>>>(row, col, dinv, cursor, srcrow, w, E);

    // ---- layer 1 ----
    agg128_k<true><<<gW, TB>>>(h, srcrow, w, start, b1, act, N);
    // ---- layer 2 ----
    gemm_k<128><<<gG128, TB, SMEMG>>>(act, W2, h, N);
    agg128_k<true><<<gW, TB>>>(h, srcrow, w, start, b2, act, N);
    // ---- layer 3 ----
    gemm_k<64><<<gG64, TB, SMEMG>>>(act, W3, h, N);
    agg64_k<<<gW, TB>>>(h, srcrow, w, start, b3, out, N);
}